// round 16
// baseline (speedup 1.0000x reference)
#include <cuda_runtime.h>
#include <cstdint>

// ModelVoxel: out[p] = f[i,j,k] with i,j,k = (int)clip((x[p]+1)/h, 0, 255),
// h = 2/255, f is 256^3 fp32.
//
// R15: exploit the clipped-normal index distribution. Each coordinate hits
// the boundary {0,255} with p=0.318, so ~24% of ALL gathers land on voxels
// with >=2 boundary coords: just 12 edge-lines + 8 corners = 12.3 KB.
// Cache those in shared memory per CTA; classify each point branchlessly
// and use predicated @p LDS / @!p LDG so non-cached lanes alone generate
// L1tex gather wavefronts (-24% gather wavefronts, -24% L2 gather sectors).
// Retains: persistent single-wave grid, depth-2 gather pipeline,
// x __ldcs / out __stcs / f evict_last policy.

#define VOX_THREADS 128

static __device__ __forceinline__ int vox1(float v) {
    const float h = 2.0f / 255.0f;           // replicate reference's fp32 h
    float p = (v + 1.0f) / h;                // same op order as reference
    p = fminf(fmaxf(p, 0.0f), 255.0f);       // clip
    return (int)p;                           // truncation == astype(int32)
}

static __device__ __forceinline__ uint64_t make_evict_last_policy() {
    uint64_t pol;
    asm("createpolicy.fractional.L2::evict_last.b64 %0, 1.0;" : "=l"(pol));
    return pol;
}

static __device__ __forceinline__ float ldg_pin_l2(const float* p, uint64_t pol) {
    float v;
    asm("ld.global.nc.L2::cache_hint.f32 %0, [%1], %2;"
        : "=f"(v) : "l"(p), "l"(pol));
    return v;
}

static __device__ __forceinline__ uint32_t smem_u32(const void* p) {
    uint32_t a;
    asm("{ .reg .u64 t; cvta.to.shared.u64 t, %1; cvt.u32.u64 %0, t; }"
        : "=r"(a) : "l"(p));
    return a;
}

// Cache layout (3072 floats):
//   [   0..1023]  s_ij: f[A][B][k]  A,B in {0,255}: slot ((a<<1|b)<<8)+k
//   [1024..2047]  s_ik: f[A][j][C]  slot 1024+((a<<1|c)<<8)+j
//   [2048..3071]  s_jk: f[i][B][C]  slot 2048+((b<<1|c)<<8)+i
// Corners live in all three; priority ij > ik > jk gives identical values.
static __device__ __forceinline__ float lookup1(
    const float* __restrict__ f, uint64_t pol, uint32_t sbase,
    int i, int j, int k)
{
    bool fi = (i == 0) | (i == 255);
    bool fj = (j == 0) | (j == 255);
    bool fk = (k == 0) | (k == 255);
    bool sij = fi & fj;
    bool sik = fi & fk;
    bool sjk = fj & fk;
    uint32_t cached = (uint32_t)(sij | sik | sjk);

    int ii = i & 1, jj = j & 1, kk = k & 1;   // 255->1, 0->0
    int saddr = 2048 + (((jj << 1) | kk) << 8) + i;      // jk (lowest prio)
    if (sik) saddr = 1024 + (((ii << 1) | kk) << 8) + j;
    if (sij) saddr = (((ii << 1) | jj) << 8) + k;
    uint32_t sa = sbase + ((uint32_t)saddr << 2);

    const float* ga = f + (((i << 16) | (j << 8)) | k);

    float v;
    asm("{\n\t"
        ".reg .pred p;\n\t"
        "setp.ne.u32 p, %1, 0;\n\t"
        "@p  ld.shared.f32 %0, [%2];\n\t"
        "@!p ld.global.nc.L2::cache_hint.f32 %0, [%3], %4;\n\t"
        "}"
        : "=f"(v) : "r"(cached), "r"(sa), "l"(ga), "l"(pol));
    return v;
}

static __device__ __forceinline__ float4 gather4c(
    const float* __restrict__ f, uint64_t pol, uint32_t sbase,
    float4 a, float4 b, float4 c)
{
    // p0:(a.x,a.y,a.z) p1:(a.w,b.x,b.y) p2:(b.z,b.w,c.x) p3:(c.y,c.z,c.w)
    float4 o;
    o.x = lookup1(f, pol, sbase, vox1(a.x), vox1(a.y), vox1(a.z));
    o.y = lookup1(f, pol, sbase, vox1(a.w), vox1(b.x), vox1(b.y));
    o.z = lookup1(f, pol, sbase, vox1(b.z), vox1(b.w), vox1(c.x));
    o.w = lookup1(f, pol, sbase, vox1(c.y), vox1(c.z), vox1(c.w));
    return o;
}

__global__ void __launch_bounds__(VOX_THREADS) voxel_pipe2c_kernel(
    const float4* __restrict__ x4,   // 3 float4s per 4 points
    const float*  __restrict__ f,    // 256^3 grid
    float4*       __restrict__ out4, // 1 float4 per 4 points
    int n4)                          // number of 4-point groups
{
    __shared__ float s_cache[3072];

    // ── Fill the edge/corner cache (24 loads/thread) ─────────────────
    for (int idx = threadIdx.x; idx < 3072; idx += VOX_THREADS) {
        int arr = idx >> 10;           // 0:ij 1:ik 2:jk
        int sub = idx & 1023;
        int ab  = sub >> 8;            // 0..3
        int tt  = sub & 255;
        int A = (ab >> 1) * 255;
        int B = (ab & 1) * 255;
        int gi;
        if (arr == 0)      gi = (A << 16) | (B << 8) | tt;
        else if (arr == 1) gi = (A << 16) | (tt << 8) | B;
        else               gi = (tt << 16) | (A << 8) | B;
        s_cache[idx] = __ldg(f + gi);
    }
    __syncthreads();
    const uint32_t sbase = smem_u32(s_cache);

    const uint64_t pol = make_evict_last_policy();
    const int stride = gridDim.x * blockDim.x;
    int t = blockIdx.x * blockDim.x + threadIdx.x;
    if (t < n4) {
        // ── Prologue ─────────────────────────────────────────────────
        const float4* p = x4 + 3 * (size_t)t;
        float4 a = __ldcs(p + 0);
        float4 b = __ldcs(p + 1);
        float4 c = __ldcs(p + 2);

        float4 o_prev = gather4c(f, pol, sbase, a, b, c);

        int tn = t + stride;
        bool more = tn < n4;
        if (more) {
            const float4* pn = x4 + 3 * (size_t)tn;
            a = __ldcs(pn + 0);
            b = __ldcs(pn + 1);
            c = __ldcs(pn + 2);
        }

        // ── Steady state: depth-2 gather pipeline ────────────────────
        while (more) {
            float4 o_next = gather4c(f, pol, sbase, a, b, c);

            int tnn = tn + stride;
            bool more2 = tnn < n4;
            if (more2) {
                const float4* pn = x4 + 3 * (size_t)tnn;
                a = __ldcs(pn + 0);
                b = __ldcs(pn + 1);
                c = __ldcs(pn + 2);
            }

            __stcs(out4 + t, o_prev);

            o_prev = o_next;
            t = tn; tn = tnn; more = more2;
        }
        __stcs(out4 + t, o_prev);
    }
}

// Tail handler for n not divisible by 4 (not needed for 16777216, but cheap).
__global__ void voxel_gather_tail_kernel(
    const float* __restrict__ x,
    const float* __restrict__ f,
    float*       __restrict__ out,
    int start, int n)
{
    int i = start + blockIdx.x * blockDim.x + threadIdx.x;
    if (i >= n) return;
    const uint64_t pol = make_evict_last_policy();
    int ix = vox1(x[3 * (size_t)i + 0]);
    int iy = vox1(x[3 * (size_t)i + 1]);
    int iz = vox1(x[3 * (size_t)i + 2]);
    out[i] = ldg_pin_l2(f + ((ix << 16) | (iy << 8) | iz), pol);
}

extern "C" void kernel_launch(void* const* d_in, const int* in_sizes, int n_in,
                              void* d_out, int out_size) {
    const float* x = (const float*)d_in[0];   // (N, 3) fp32
    const float* f = (const float*)d_in[1];   // (256,256,256) fp32
    float* out = (float*)d_out;               // (N,) fp32

    int n  = in_sizes[0] / 3;                 // number of points
    int n4 = n / 4;

    if (n4 > 0) {
        int threads = VOX_THREADS;
        // Let the driver budget a big smem carveout so 12 KB/CTA doesn't
        // cap residency below the register limit.
        cudaFuncSetAttribute(voxel_pipe2c_kernel,
                             cudaFuncAttributePreferredSharedMemoryCarveout, 100);
        // Persistent grid sized to actual residency (regs+smem dependent).
        int sms = 152;
        cudaDeviceGetAttribute(&sms, cudaDevAttrMultiProcessorCount, 0);
        int per_sm = 12;
        cudaOccupancyMaxActiveBlocksPerMultiprocessor(
            &per_sm, voxel_pipe2c_kernel, threads, 0);
        if (per_sm < 1) per_sm = 1;
        int blocks = sms * per_sm;
        int max_blocks = (n4 + threads - 1) / threads;
        if (blocks > max_blocks) blocks = max_blocks;
        voxel_pipe2c_kernel<<<blocks, threads>>>(
            (const float4*)x, f, (float4*)out, n4);
    }
    int rem_start = n4 * 4;
    if (rem_start < n) {
        int rem = n - rem_start;
        voxel_gather_tail_kernel<<<(rem + 255) / 256, 256>>>(
            x, f, out, rem_start, n);
    }
}

// round 17
// speedup vs baseline: 3.1926x; 3.1926x over previous
#include <cuda_runtime.h>
#include <cstdint>

// ModelVoxel: out[p] = f[i,j,k] with i,j,k = (int)clip((x[p]+1)/h, 0, 255),
// h = 2/255, f is 256^3 fp32 (64 MB, mostly L2-resident via evict_last hint).
//
// R16: revert R15's smem-cache experiment (predicated LDS/LDG pair
// serialized every gather -> 255us). Back to the proven R14 body:
// persistent grid + depth-2 gather pipeline + cache-policy split.
// Single tweak: 64-thread blocks. At 40 regs that yields 25 CTAs/SM =
// 50 warps (78% occ, vs 48/75% at 128-thr) and finer tail granularity,
// with the compiled hot body byte-identical.
//  - x   -> __ldcs (evict-first streaming)
//  - out -> __stcs
//  - f   -> ld.global.nc.L2::cache_hint + createpolicy evict_last
//           (edge/corner hot set stays L1-resident automatically)

#define VOX_THREADS 64

static __device__ __forceinline__ int vox1(float v) {
    const float h = 2.0f / 255.0f;           // replicate reference's fp32 h
    float p = (v + 1.0f) / h;                // same op order as reference
    p = fminf(fmaxf(p, 0.0f), 255.0f);       // clip
    return (int)p;                           // truncation == astype(int32)
}

static __device__ __forceinline__ uint64_t make_evict_last_policy() {
    uint64_t pol;
    asm("createpolicy.fractional.L2::evict_last.b64 %0, 1.0;" : "=l"(pol));
    return pol;
}

static __device__ __forceinline__ float ldg_pin_l2(const float* p, uint64_t pol) {
    float v;
    asm("ld.global.nc.L2::cache_hint.f32 %0, [%1], %2;"
        : "=f"(v) : "l"(p), "l"(pol));
    return v;
}

static __device__ __forceinline__ float4 gather4(
    const float* __restrict__ f, uint64_t pol,
    float4 a, float4 b, float4 c)
{
    // p0:(a.x,a.y,a.z) p1:(a.w,b.x,b.y) p2:(b.z,b.w,c.x) p3:(c.y,c.z,c.w)
    int i0 = (vox1(a.x) << 16) | (vox1(a.y) << 8) | vox1(a.z);
    int i1 = (vox1(a.w) << 16) | (vox1(b.x) << 8) | vox1(b.y);
    int i2 = (vox1(b.z) << 16) | (vox1(b.w) << 8) | vox1(c.x);
    int i3 = (vox1(c.y) << 16) | (vox1(c.z) << 8) | vox1(c.w);
    float4 o;
    o.x = ldg_pin_l2(f + i0, pol);
    o.y = ldg_pin_l2(f + i1, pol);
    o.z = ldg_pin_l2(f + i2, pol);
    o.w = ldg_pin_l2(f + i3, pol);
    return o;
}

__global__ void __launch_bounds__(VOX_THREADS) voxel_pipe2_kernel(
    const float4* __restrict__ x4,   // 3 float4s per 4 points
    const float*  __restrict__ f,    // 256^3 grid
    float4*       __restrict__ out4, // 1 float4 per 4 points
    int n4)                          // number of 4-point groups
{
    const uint64_t pol = make_evict_last_policy();
    const int stride = gridDim.x * blockDim.x;
    int t = blockIdx.x * blockDim.x + threadIdx.x;
    if (t >= n4) return;

    // ── Prologue: group t loaded, gathers issued; group t+stride loading ──
    const float4* p = x4 + 3 * (size_t)t;
    float4 a = __ldcs(p + 0);
    float4 b = __ldcs(p + 1);
    float4 c = __ldcs(p + 2);

    float4 o_prev = gather4(f, pol, a, b, c);   // gathers for t in flight

    int tn = t + stride;
    bool more = tn < n4;
    if (more) {
        const float4* pn = x4 + 3 * (size_t)tn;
        a = __ldcs(pn + 0);
        b = __ldcs(pn + 1);
        c = __ldcs(pn + 2);
    }

    // ── Steady state: depth-2 gather pipeline ────────────────────────
    while (more) {
        // Issue gathers for tn (x arrived last iteration).
        float4 o_next = gather4(f, pol, a, b, c);

        // Issue x loads for tn+stride; they fly under o_next's gathers.
        int tnn = tn + stride;
        bool more2 = tnn < n4;
        if (more2) {
            const float4* pn = x4 + 3 * (size_t)tnn;
            a = __ldcs(pn + 0);
            b = __ldcs(pn + 1);
            c = __ldcs(pn + 2);
        }

        // Retire t: its gathers are a full iteration old -> no stall.
        __stcs(out4 + t, o_prev);

        o_prev = o_next;
        t = tn; tn = tnn; more = more2;
    }
    __stcs(out4 + t, o_prev);
}

// Tail handler for n not divisible by 4 (not needed for 16777216, but cheap).
__global__ void voxel_gather_tail_kernel(
    const float* __restrict__ x,
    const float* __restrict__ f,
    float*       __restrict__ out,
    int start, int n)
{
    int i = start + blockIdx.x * blockDim.x + threadIdx.x;
    if (i >= n) return;
    const uint64_t pol = make_evict_last_policy();
    int ix = vox1(x[3 * (size_t)i + 0]);
    int iy = vox1(x[3 * (size_t)i + 1]);
    int iz = vox1(x[3 * (size_t)i + 2]);
    out[i] = ldg_pin_l2(f + ((ix << 16) | (iy << 8) | iz), pol);
}

extern "C" void kernel_launch(void* const* d_in, const int* in_sizes, int n_in,
                              void* d_out, int out_size) {
    const float* x = (const float*)d_in[0];   // (N, 3) fp32
    const float* f = (const float*)d_in[1];   // (256,256,256) fp32
    float* out = (float*)d_out;               // (N,) fp32

    int n  = in_sizes[0] / 3;                 // number of points
    int n4 = n / 4;

    if (n4 > 0) {
        int threads = VOX_THREADS;
        // Persistent grid sized to actual residency (reg-count dependent).
        int sms = 152;
        cudaDeviceGetAttribute(&sms, cudaDevAttrMultiProcessorCount, 0);
        int per_sm = 16;
        cudaOccupancyMaxActiveBlocksPerMultiprocessor(
            &per_sm, voxel_pipe2_kernel, threads, 0);
        if (per_sm < 1) per_sm = 1;
        int blocks = sms * per_sm;
        int max_blocks = (n4 + threads - 1) / threads;
        if (blocks > max_blocks) blocks = max_blocks;
        voxel_pipe2_kernel<<<blocks, threads>>>(
            (const float4*)x, f, (float4*)out, n4);
    }
    int rem_start = n4 * 4;
    if (rem_start < n) {
        int rem = n - rem_start;
        voxel_gather_tail_kernel<<<(rem + 255) / 256, 256>>>(
            x, f, out, rem_start, n);
    }
}